// round 1
// baseline (speedup 1.0000x reference)
#include <cuda_runtime.h>

#define TT 11
#define THREADS 256
#define ITEMS 16
#define PER_BLOCK (THREADS * ITEMS)   // 4096 atoms per block
#define BMAX 8192                     // supports up to 33.5M atoms

// -------- scratch (no cudaMalloc allowed) --------
__device__ int g_blockHist[BMAX * 16];
__device__ int g_blockBase[BMAX * 16];
__device__ int g_counts[16];
__device__ int g_offsets[16];
__device__ int g_is64;

// -------- dtype detection: int64 vs int32 atom_types --------
// If data is int32, reading int64 words gives (lo + hi*2^32); hi is the next
// type value which is nonzero with overwhelming probability over 2048 samples.
__global__ void k_detect(const void* __restrict__ types, int N) {
    __shared__ int bad;
    if (threadIdx.x == 0) bad = 0;
    __syncthreads();
    const long long* t64 = (const long long*)types;
    int n = min(2048, N / 2);   // safe to read in BOTH layouts
    for (int i = threadIdx.x; i < n; i += 256) {
        long long v = t64[i];
        if (v < 0 || v >= TT) bad = 1;
    }
    __syncthreads();
    if (threadIdx.x == 0) g_is64 = bad ? 0 : 1;
}

__device__ __forceinline__ int loadType(const void* p, int i, int is64) {
    return is64 ? (int)((const long long*)p)[i] : ((const int*)p)[i];
}

// -------- pass 1: per-block histogram --------
__global__ void __launch_bounds__(THREADS) k_hist(const void* __restrict__ types, int N) {
    __shared__ int h[8][16];
    int tid = threadIdx.x;
    int is64 = g_is64;
    if (tid < 128) ((int*)h)[tid] = 0;
    __syncthreads();
    int base = blockIdx.x * PER_BLOCK;
    int n = min(PER_BLOCK, N - base);
    int w = tid >> 5;
    for (int i = tid; i < n; i += THREADS) {
        int t = loadType(types, base + i, is64);
        atomicAdd(&h[w][t], 1);
    }
    __syncthreads();
    if (tid < 16) {
        int s = 0;
#pragma unroll
        for (int ww = 0; ww < 8; ww++) s += h[ww][tid];
        g_blockHist[blockIdx.x * 16 + tid] = s;
    }
}

// -------- pass 2: per-type exclusive scan over blocks --------
__global__ void k_scan(int B) {
    int t = blockIdx.x;          // one block per type
    __shared__ int s[1024];
    int tid = threadIdx.x;
    int carry = 0;
    for (int start = 0; start < B; start += 1024) {
        int i = start + tid;
        int v = (i < B) ? g_blockHist[i * 16 + t] : 0;
        s[tid] = v;
        __syncthreads();
        for (int off = 1; off < 1024; off <<= 1) {
            int x = (tid >= off) ? s[tid - off] : 0;
            __syncthreads();
            s[tid] += x;
            __syncthreads();
        }
        if (i < B) g_blockBase[i * 16 + t] = carry + s[tid] - v;  // exclusive
        carry += s[1023];
        __syncthreads();
    }
    if (tid == 0) g_counts[t] = carry;
}

// -------- pass 3a: type offsets + write counts/offsets tail --------
__global__ void k_offsets(float* outTail, int writeTail) {
    if (threadIdx.x == 0) {
        int run = 0;
        for (int t = 0; t < TT; t++) {
            int c = g_counts[t];
            g_offsets[t] = run;
            if (writeTail) { outTail[t] = (float)c; outTail[TT + t] = (float)run; }
            run += c;
        }
    }
}

// field extraction from 10-bit packed counters (types 0..5 in q0, 6..10 in q1)
__device__ __forceinline__ int fieldOf(unsigned long long q0, unsigned long long q1, int t) {
    unsigned long long q = (t < 6) ? q0 : q1;
    int sh = (t < 6) ? 10 * t : 10 * (t - 6);
    return (int)((q >> sh) & 1023ull);
}

// -------- pass 3b: stable rank + smem staging + coalesced segment copy --------
__global__ void __launch_bounds__(THREADS) k_scatter(const float* __restrict__ coords,
                                                     const void* __restrict__ types,
                                                     float* __restrict__ out, int N) {
    extern __shared__ char smem[];
    unsigned long long* sWT0 = (unsigned long long*)smem;           // 8
    unsigned long long* sWT1 = sWT0 + 8;                            // 8
    float* sC = (float*)(sWT1 + 8);                                 // PER_BLOCK*3 floats
    unsigned char* sT = (unsigned char*)(sC + PER_BLOCK * 3);       // PER_BLOCK bytes
    int* sCnt = (int*)(sT + PER_BLOCK);                             // TT*257 ints
    int* sWB = sCnt + TT * 257;                                     // 8*16
    int* sTot = sWB + 128;                                          // 16
    int* sLto = sTot + 16;                                          // 16

    int tid = threadIdx.x;
    int lane = tid & 31;
    int w = tid >> 5;
    int blk = blockIdx.x;
    int base = blk * PER_BLOCK;
    int nblk = min(PER_BLOCK, N - base);
    int is64 = g_is64;

    // stage types (coalesced) into bytes
    for (int j = tid; j < nblk; j += THREADS)
        sT[j] = (unsigned char)loadType(types, base + j, is64);
    __syncthreads();

    int myBase = tid * ITEMS;
    int myCnt = nblk - myBase;
    myCnt = myCnt < 0 ? 0 : (myCnt > ITEMS ? ITEMS : myCnt);

    // per-thread histogram packed into 10-bit fields (count <= 16)
    unsigned long long p0 = 0, p1 = 0;
    for (int j = 0; j < myCnt; j++) {
        int t = sT[myBase + j];
        if (t < 6) p0 += 1ull << (10 * t);
        else       p1 += 1ull << (10 * (t - 6));
    }
    unsigned long long m0 = p0, m1 = p1;
    // warp inclusive scan (warp total <= 512 < 1024, no field overflow)
#pragma unroll
    for (int d = 1; d < 32; d <<= 1) {
        unsigned long long n0 = __shfl_up_sync(0xffffffffu, p0, d);
        unsigned long long n1 = __shfl_up_sync(0xffffffffu, p1, d);
        if (lane >= d) { p0 += n0; p1 += n1; }
    }
    unsigned long long e0 = p0 - m0, e1 = p1 - m1;   // exclusive within warp
    if (lane == 31) { sWT0[w] = p0; sWT1[w] = p1; }
    __syncthreads();
    // cross-warp exclusive scan (unpacked; block total may exceed 10 bits)
    if (tid < TT) {
        int run = 0;
        for (int ww = 0; ww < 8; ww++) {
            sWB[ww * 16 + tid] = run;
            run += fieldOf(sWT0[ww], sWT1[ww], tid);
        }
        sTot[tid] = run;
    }
    __syncthreads();
    if (tid == 0) {
        int run = 0;
        for (int t = 0; t < TT; t++) { sLto[t] = run; run += sTot[t]; }
    }
    __syncthreads();

    // per-thread starting slot per type (owned cells, stride 257 => bank spread)
#pragma unroll
    for (int t = 0; t < TT; t++)
        sCnt[t * 257 + tid] = sLto[t] + sWB[w * 16 + t] + fieldOf(e0, e1, t);
    __syncthreads();

    // replay in original order: stable placement into shared, sorted by type
    const float* cbase = coords + (long long)3 * (base + myBase);
    for (int j = 0; j < myCnt; j++) {
        int t = sT[myBase + j];
        int idx = t * 257 + tid;
        int r = sCnt[idx];
        sCnt[idx] = r + 1;
        float c0 = cbase[3 * j + 0];
        float c1 = cbase[3 * j + 1];
        float c2 = cbase[3 * j + 2];
        sC[3 * r + 0] = c0;
        sC[3 * r + 1] = c1;
        sC[3 * r + 2] = c2;
    }
    __syncthreads();

    // coalesced copy-out, one contiguous segment per type
    for (int t = 0; t < TT; t++) {
        int cnt3 = sTot[t] * 3;
        long long gb = (long long)(g_offsets[t] + g_blockBase[blk * 16 + t]) * 3;
        int sb = sLto[t] * 3;
        for (int i = tid; i < cnt3; i += THREADS)
            out[gb + i] = sC[sb + i];
    }
}

extern "C" void kernel_launch(void* const* d_in, const int* in_sizes, int n_in,
                              void* d_out, int out_size) {
    const float* coords = (const float*)d_in[0];
    const void* types = d_in[1];
    int N = in_sizes[1];
    int B = (N + PER_BLOCK - 1) / PER_BLOCK;
    float* out = (float*)d_out;
    long long coordsOut = (long long)3 * N;
    int writeTail = (out_size >= (int)(coordsOut + 2 * TT)) ? 1 : 0;

    // smem: 128 + 49152 + 4096 + 11308 + 512 + 64 + 64 = 65324 -> round up
    const int SMEM = 66000;
    cudaFuncSetAttribute(k_scatter, cudaFuncAttributeMaxDynamicSharedMemorySize, SMEM);

    k_detect<<<1, 256>>>(types, N);
    k_hist<<<B, THREADS>>>(types, N);
    k_scan<<<TT, 1024>>>(B);
    k_offsets<<<1, 32>>>(out + coordsOut, writeTail);
    k_scatter<<<B, THREADS, SMEM>>>(coords, types, out, N);
}

// round 3
// speedup vs baseline: 1.3911x; 1.3911x over previous
#include <cuda_runtime.h>

#define TT 11
#define THREADS 256
#define ITEMS 16
#define PER_BLOCK 4096
#define BMAX 8192

__device__ int g_blockHist[BMAX * 16];
__device__ int g_blockBase[BMAX * 16];
__device__ int g_offsets[16];

// field extraction from 10-bit packed counters (types 0..5 in q0, 6..10 in q1)
__device__ __forceinline__ int fieldOf(unsigned long long q0, unsigned long long q1, int t) {
    unsigned long long q = (t < 6) ? q0 : q1;
    int sh = (t < 6) ? 10 * t : 10 * (t - 6);
    return (int)((q >> sh) & 1023ull);
}

// per-block dtype detection: read 256 int64 words; if data is int32 the hi half
// of each word is the next type value (nonzero w.p. 10/11 per sample).
__device__ __forceinline__ int detect64(const void* types, int N, int base) {
    const long long* t64 = (const long long*)types;
    int wmax = N >> 1;
    int wi = (base >> 1) + threadIdx.x;
    if (wi >= wmax) wi = wmax - 1;
    long long v = t64[wi];
    return __syncthreads_and(v >= 0 && v < TT);
}

__device__ __forceinline__ void loadTypes16(const void* types, int gbase, int is64,
                                            unsigned int tp[4]) {
    if (is64) {
        const longlong2* p = (const longlong2*)((const long long*)types + gbase);
#pragma unroll
        for (int k = 0; k < 4; k++) {
            longlong2 a = p[2 * k], b = p[2 * k + 1];
            tp[k] = (unsigned)a.x | ((unsigned)a.y << 8) |
                    ((unsigned)b.x << 16) | ((unsigned)b.y << 24);
        }
    } else {
        const int4* p = (const int4*)((const int*)types + gbase);
#pragma unroll
        for (int k = 0; k < 4; k++) {
            int4 a = p[k];
            tp[k] = (unsigned)a.x | ((unsigned)a.y << 8) |
                    ((unsigned)a.z << 16) | ((unsigned)a.w << 24);
        }
    }
}

__device__ __forceinline__ int scalarType(const void* types, int i, int is64) {
    return is64 ? (int)((const long long*)types)[i] : ((const int*)types)[i];
}

// -------- pass 1: per-block histogram (register packed counters, no atomics) -----
__global__ void __launch_bounds__(THREADS) k_hist(const void* __restrict__ types, int N) {
    __shared__ unsigned long long sW0[8], sW1[8];
    int tid = threadIdx.x, lane = tid & 31, w = tid >> 5;
    int base = blockIdx.x * PER_BLOCK;
    int is64 = detect64(types, N, base);

    int myBase = base + tid * ITEMS;
    unsigned long long p0 = 0, p1 = 0;
    if (base + PER_BLOCK <= N) {
        unsigned tp[4];
        loadTypes16(types, myBase, is64, tp);
#pragma unroll
        for (int j = 0; j < ITEMS; j++) {
            int t = (tp[j >> 2] >> ((j & 3) * 8)) & 0xFF;
            if (t < 6) p0 += 1ull << (10 * t); else p1 += 1ull << (10 * (t - 6));
        }
    } else {
        int cnt = N - myBase; cnt = cnt < 0 ? 0 : (cnt > ITEMS ? ITEMS : cnt);
        for (int j = 0; j < cnt; j++) {
            int t = scalarType(types, myBase + j, is64);
            if (t < 6) p0 += 1ull << (10 * t); else p1 += 1ull << (10 * (t - 6));
        }
    }
#pragma unroll
    for (int d = 16; d; d >>= 1) {
        p0 += __shfl_xor_sync(0xffffffffu, p0, d);
        p1 += __shfl_xor_sync(0xffffffffu, p1, d);
    }
    if (lane == 0) { sW0[w] = p0; sW1[w] = p1; }
    __syncthreads();
    if (tid < TT) {
        int s = 0;
#pragma unroll
        for (int ww = 0; ww < 8; ww++) s += fieldOf(sW0[ww], sW1[ww], tid);
        g_blockHist[blockIdx.x * 16 + tid] = s;
    }
}

// -------- pass 2 (fused): per-type scan over blocks + type offsets + out tail ----
__global__ void k_scanoff(int B, float* outTail, int writeTail) {
    __shared__ int sCounts[16];
    int tid = threadIdx.x, w = tid >> 5, lane = tid & 31;
    if (w < TT) {
        int chunk = (B + 31) / 32;
        int s0 = lane * chunk;
        int cnt = B - s0; cnt = cnt < 0 ? 0 : (cnt > chunk ? chunk : cnt);
        int sum = 0;
        for (int j = 0; j < cnt; j++) sum += g_blockHist[(s0 + j) * 16 + w];
        int inc = sum;
#pragma unroll
        for (int d = 1; d < 32; d <<= 1) {
            int n = __shfl_up_sync(0xffffffffu, inc, d);
            if (lane >= d) inc += n;
        }
        int run = inc - sum;   // exclusive across lanes
        for (int j = 0; j < cnt; j++) {
            int v = g_blockHist[(s0 + j) * 16 + w];   // L2 hit
            g_blockBase[(s0 + j) * 16 + w] = run;
            run += v;
        }
        if (lane == 31) sCounts[w] = inc;   // total for this type
    }
    __syncthreads();
    if (tid == 0) {
        int run = 0;
        for (int t = 0; t < TT; t++) {
            int c = sCounts[t];
            g_offsets[t] = run;
            if (writeTail) { outTail[t] = (float)c; outTail[TT + t] = (float)run; }
            run += c;
        }
    }
}

// -------- pass 3: stable rank + smem staging + coalesced segment copy-out --------
__global__ void __launch_bounds__(THREADS, 3) k_scatter(const float* __restrict__ coords,
                                                        const void* __restrict__ types,
                                                        float* __restrict__ out, int N) {
    extern __shared__ char smem[];
    // 8B-aligned arrays FIRST (offset 0) — misplacing these after an odd number
    // of ints caused the round-2 misaligned-address trap (STS.64 @ 4 mod 8).
    unsigned long long* sW0 = (unsigned long long*)smem;       // 8  (offset 0)
    unsigned long long* sW1 = sW0 + 8;                         // 8  (offset 64)
    float* sC = (float*)(sW1 + 8);                             // PER_BLOCK*3 floats @128
    int* sCnt = (int*)(sC + PER_BLOCK * 3);                    // TT*257
    int* sWB = sCnt + TT * 257;                                // 8*16
    int* sTot = sWB + 128;                                     // 16
    int* sLto = sTot + 16;                                     // 16

    int tid = threadIdx.x, lane = tid & 31, w = tid >> 5;
    int blk = blockIdx.x, base = blk * PER_BLOCK;
    int nblk = min(PER_BLOCK, N - base);
    int is64 = detect64(types, N, base);

    int myBase = tid * ITEMS;
    int myCnt = nblk - myBase; myCnt = myCnt < 0 ? 0 : (myCnt > ITEMS ? ITEMS : myCnt);
    bool full = (myCnt == ITEMS);

    // types -> 4 packed-byte registers
    unsigned tp[4];
    if (full) {
        loadTypes16(types, base + myBase, is64, tp);
    } else {
        tp[0] = tp[1] = tp[2] = tp[3] = 0;
        for (int j = 0; j < myCnt; j++)
            tp[j >> 2] |= (unsigned)scalarType(types, base + myBase + j, is64) << ((j & 3) * 8);
    }
    // coords -> 48 registers via 12x LDG.128 (high MLP, coalesced lines)
    float cv[48];
    if (full) {
        const float4* cp = (const float4*)(coords + (size_t)3 * (base + myBase));
#pragma unroll
        for (int k = 0; k < 12; k++) {
            float4 v = cp[k];
            cv[4 * k] = v.x; cv[4 * k + 1] = v.y; cv[4 * k + 2] = v.z; cv[4 * k + 3] = v.w;
        }
    } else {
        const float* cp = coords + (size_t)3 * (base + myBase);
        for (int i = 0; i < 3 * myCnt; i++) cv[i] = cp[i];
    }

    // per-thread packed histogram
    unsigned long long p0 = 0, p1 = 0;
#pragma unroll
    for (int j = 0; j < ITEMS; j++) {
        if (j < myCnt) {
            int t = (tp[j >> 2] >> ((j & 3) * 8)) & 0xFF;
            if (t < 6) p0 += 1ull << (10 * t); else p1 += 1ull << (10 * (t - 6));
        }
    }
    unsigned long long m0 = p0, m1 = p1;
#pragma unroll
    for (int d = 1; d < 32; d <<= 1) {
        unsigned long long n0 = __shfl_up_sync(0xffffffffu, p0, d);
        unsigned long long n1 = __shfl_up_sync(0xffffffffu, p1, d);
        if (lane >= d) { p0 += n0; p1 += n1; }
    }
    unsigned long long e0 = p0 - m0, e1 = p1 - m1;   // exclusive within warp
    if (lane == 31) { sW0[w] = p0; sW1[w] = p1; }
    __syncthreads();
    if (tid < TT) {
        int run = 0;
#pragma unroll
        for (int ww = 0; ww < 8; ww++) {
            sWB[ww * 16 + tid] = run;
            run += fieldOf(sW0[ww], sW1[ww], tid);
        }
        sTot[tid] = run;
    }
    __syncthreads();
    if (tid == 0) {
        int run = 0;
        for (int t = 0; t < TT; t++) { sLto[t] = run; run += sTot[t]; }
    }
    __syncthreads();
#pragma unroll
    for (int t = 0; t < TT; t++)
        sCnt[t * 257 + tid] = sLto[t] + sWB[w * 16 + t] + fieldOf(e0, e1, t);
    __syncthreads();

    // stable replay into shared, grouped by type
#pragma unroll
    for (int j = 0; j < ITEMS; j++) {
        if (j < myCnt) {
            int t = (tp[j >> 2] >> ((j & 3) * 8)) & 0xFF;
            int idx = t * 257 + tid;
            int r = sCnt[idx];
            sCnt[idx] = r + 1;
            sC[3 * r + 0] = cv[3 * j + 0];
            sC[3 * r + 1] = cv[3 * j + 1];
            sC[3 * r + 2] = cv[3 * j + 2];
        }
    }
    __syncthreads();

    // coalesced copy-out, one contiguous segment per type
    for (int t = 0; t < TT; t++) {
        int cnt3 = sTot[t] * 3;
        size_t gb = (size_t)(g_offsets[t] + g_blockBase[blk * 16 + t]) * 3;
        int sb = sLto[t] * 3;
        for (int i = tid; i < cnt3; i += THREADS)
            out[gb + i] = sC[sb + i];
    }
}

extern "C" void kernel_launch(void* const* d_in, const int* in_sizes, int n_in,
                              void* d_out, int out_size) {
    const float* coords = (const float*)d_in[0];
    const void* types = d_in[1];
    int N = in_sizes[1];
    int B = (N + PER_BLOCK - 1) / PER_BLOCK;
    float* out = (float*)d_out;
    long long coordsOut = (long long)3 * N;
    int writeTail = ((long long)out_size >= coordsOut + 2 * TT) ? 1 : 0;

    const int SMEM = 61440;
    cudaFuncSetAttribute(k_scatter, cudaFuncAttributeMaxDynamicSharedMemorySize, SMEM);

    k_hist<<<B, THREADS>>>(types, N);
    k_scanoff<<<1, 352>>>(B, out + coordsOut, writeTail);
    k_scatter<<<B, THREADS, SMEM>>>(coords, types, out, N);
}